// round 2
// baseline (speedup 1.0000x reference)
#include <cuda_runtime.h>

#define BB 2
#define NN 4096
#define CC 128
#define CIN 64
#define KK 16
#define GG 8
#define PPB (NN*KK)       // 65536 positions per batch
#define PP (BB*PPB)       // 131072 total positions
#define EPSF 1e-5f
#define CNTF 1048576.0f   // 16 * 4096 * 16 elements per (b,g)

// ---------------- scratch (device globals; no allocs allowed) ----------------
__device__ float g_f1T[BB*NN*CC];
__device__ float g_f2T[BB*NN*CC];
__device__ float g_g1T[BB*NN*CC];
__device__ float g_g2T[BB*NN*CC];
__device__ float g_fn1T[BB*NN*CC];
__device__ float g_fn2T[BB*NN*CC];
__device__ int   g_idx12[BB*NN*KK];
__device__ int   g_idx21[BB*NN*KK];
__device__ float g_dir12[BB*NN*KK*3];
__device__ float g_dir21[BB*NN*KK*3];
__device__ float g_bufA[CC*PP];      // channel-major [c][p]
__device__ float g_bufB[CC*PP];
__device__ float g_pool[BB*NN*CC];   // position-major [b][n][c]
__device__ float g_stats[8*BB*GG*2]; // per-stage (sum, sumsq)
__device__ float g_WT[3*CC*CC];      // transposed mlp weights: WT[c][o]

// ---------------- f32x2 helpers ----------------------------------------------
__device__ __forceinline__ unsigned long long bcast2(float x){
    unsigned long long r;
    asm("mov.b64 %0, {%1,%1};" : "=l"(r) : "f"(x));
    return r;
}
__device__ __forceinline__ void fma2(unsigned long long &acc, unsigned long long a, unsigned long long b){
    asm("fma.rn.f32x2 %0, %1, %2, %0;" : "+l"(acc) : "l"(a), "l"(b));
}
__device__ __forceinline__ float2 unpk2(unsigned long long v){
    float2 f;
    asm("mov.b64 {%0,%1}, %2;" : "=f"(f.x), "=f"(f.y) : "l"(v));
    return f;
}

// ---------------- input 1x1 convs: feat -> transposed features [b][n][c] ----
__global__ void k_conv1d_in(const float* __restrict__ feat1, const float* __restrict__ feat2,
                            const float* __restrict__ t11_w, const float* __restrict__ t11_b,
                            const float* __restrict__ t22_w, const float* __restrict__ t22_b) {
    int job = blockIdx.z;   // 0:f1=t11@feat1 1:f2=t22@feat2 2:g1=t11@feat2 3:g2=t22@feat1
    int b = blockIdx.y;
    int n0 = blockIdx.x * 32;
    const float* x    = (job==0||job==3) ? feat1 : feat2;
    const float* w    = (job==0||job==2) ? t11_w : t22_w;
    const float* bias = (job==0||job==2) ? t11_b : t22_b;
    float* outp = (job==0) ? g_f1T : (job==1) ? g_f2T : (job==2) ? g_g1T : g_g2T;

    __shared__ float xs[CIN*33];
    int t = threadIdx.x;   // 128
    for (int l=t; l<CIN*32; l+=128) {
        int c=l>>5, j=l&31;
        xs[c*33+j] = x[(b*CIN+c)*NN + n0+j];
    }
    __syncthreads();
    int o = t;
    float wr[CIN];
#pragma unroll
    for (int c=0;c<CIN;c++) wr[c] = w[o*CIN+c];
    float bv = bias[o];
    for (int j=0;j<32;j++){
        float acc = bv;
#pragma unroll
        for (int c=0;c<CIN;c++) acc += wr[c]*xs[c*33+j];
        outp[(b*NN+n0+j)*CC + o] = acc;
    }
}

// ---------------- KNN (k=16): 4-way candidate split + shuffle merge ----------
__global__ void __launch_bounds__(512) k_knn(const float* __restrict__ pc1, const float* __restrict__ pc2) {
    int dir = blockIdx.z;
    const float* pq   = (dir==0) ? pc1 : pc2;
    const float* pcnd = (dir==0) ? pc2 : pc1;
    int*   idxo = (dir==0) ? g_idx12 : g_idx21;
    float* diro = (dir==0) ? g_dir12 : g_dir21;
    int b = blockIdx.y;
    int t = threadIdx.x;
    int qi = t >> 2;        // query within block (0..127)
    int sl = t & 3;         // candidate slice (0..3)
    int n = blockIdx.x*128 + qi;

    float qx = pq[(b*3+0)*NN+n], qy = pq[(b*3+1)*NN+n], qz = pq[(b*3+2)*NN+n];
    float s1 = qx*qx + qy*qy + qz*qz;

    float bd[KK]; int bi[KK];
#pragma unroll
    for (int k=0;k<KK;k++){ bd[k]=1e30f; bi[k]=0; }
    float worst = 1e30f;

    __shared__ float4 sc[1024];
    // round r stages 256 candidates from each slice's range
    for (int r=0; r<4; r++) {
        __syncthreads();
        for (int i=t; i<1024; i+=512) {
            int sl2 = i >> 8, ii = i & 255;
            int m = sl2*1024 + r*256 + ii;
            float x = pcnd[(b*3+0)*NN+m];
            float y = pcnd[(b*3+1)*NN+m];
            float z = pcnd[(b*3+2)*NN+m];
            sc[i] = make_float4(x,y,z, x*x+y*y+z*z);
        }
        __syncthreads();
        int mbase = sl*1024 + r*256;
        const float4* base = &sc[sl*256];
        for (int i=0;i<256;i++) {
            float4 c = base[i];
            float d = s1 + c.w - 2.f*(qx*c.x + qy*c.y + qz*c.z);
            if (d < worst) {
                int j = KK-1;
                while (j>0 && bd[j-1] > d) { bd[j]=bd[j-1]; bi[j]=bi[j-1]; j--; }
                bd[j]=d; bi[j]=mbase+i;
                worst = bd[KK-1];
            }
        }
    }
    // tournament merge within the 4 lanes of a query (same warp: lanes qi%8*4+sl)
    const unsigned mask = 0xffffffffu;
#pragma unroll
    for (int off=1; off<=2; off<<=1) {
        float od[KK]; int oi[KK];
#pragma unroll
        for (int k=0;k<KK;k++){
            od[k] = __shfl_xor_sync(mask, bd[k], off);
            oi[k] = __shfl_xor_sync(mask, bi[k], off);
        }
        if ((sl & (2*off-1)) == 0) {
            for (int k=0;k<KK;k++){
                float d = od[k];
                if (d >= worst) break;   // od sorted ascending
                int j = KK-1;
                while (j>0 && bd[j-1] > d) { bd[j]=bd[j-1]; bi[j]=bi[j-1]; j--; }
                bd[j]=d; bi[j]=oi[k];
                worst = bd[KK-1];
            }
        }
    }
    // broadcast lane sl==0's final indices to the 4 lanes; each writes 4 k's
    int lane = t & 31;
    int src = lane & ~3;
    int fbi[KK];
#pragma unroll
    for (int k=0;k<KK;k++) fbi[k] = __shfl_sync(mask, bi[k], src);
    for (int kk=0; kk<4; kk++){
        int k = sl*4 + kk;
        int m = fbi[k];
        idxo[(b*NN+n)*KK+k] = m;
        float dx = pcnd[(b*3+0)*NN+m] - qx;
        float dy = pcnd[(b*3+1)*NN+m] - qy;
        float dz = pcnd[(b*3+2)*NN+m] - qz;
        diro[((b*NN+n)*KK+k)*3+0] = dx;
        diro[((b*NN+n)*KK+k)*3+1] = dy;
        diro[((b*NN+n)*KK+k)*3+2] = dz;
    }
}

// ---------------- weight transpose (m1a, m1b, m2a) --------------------------
__global__ void k_transw(const float* __restrict__ m1a, const float* __restrict__ m1b,
                         const float* __restrict__ m2a) {
    const float* src = (blockIdx.x==0) ? m1a : (blockIdx.x==1) ? m1b : m2a;
    float* dst = g_WT + blockIdx.x*CC*CC;
    for (int l=threadIdx.x; l<CC*CC; l+=256){
        int o=l>>7, c=l&127;
        dst[c*CC+o] = src[l];
    }
}

// ---------------- gather prologue of a cross block ---------------------------
__global__ void k_gather(const int* __restrict__ idx, const float* __restrict__ dirv,
                         const float* __restrict__ p1T, const float* __restrict__ p2T,
                         const float* __restrict__ pos_w, const float* __restrict__ pos_b,
                         float* __restrict__ X, float* __restrict__ stats) {
    int b = blockIdx.y, n0 = blockIdx.x*8, c = threadIdx.x;
    float pw0 = pos_w[c*3+0], pw1 = pos_w[c*3+1], pw2 = pos_w[c*3+2], pb = pos_b[c];
    __shared__ float sh[CC*33];
    float sum=0.f, sq=0.f;
    int pbase = b*PPB + n0*KK;
    int lane = threadIdx.x & 31, r0 = threadIdx.x >> 5;

    for (int half=0; half<4; half++){
        for (int nn=0; nn<2; nn++){
            int n = n0 + half*2 + nn;
            float p1v = p1T[(b*NN+n)*CC + c];
            const int* ip = &idx[(b*NN+n)*KK];
            const float* dp0 = &dirv[(b*NN+n)*KK*3];
            for (int k=0;k<KK;k++){
                int m = ip[k];
                float pf = pw0*dp0[k*3+0] + pw1*dp0[k*3+1] + pw2*dp0[k*3+2] + pb;
                float v = p2T[(b*NN+m)*CC + c] + p1v + pf;
                sum += v; sq += v*v;
                sh[c*33 + nn*KK + k] = v;
            }
        }
        __syncthreads();
        int po = pbase + half*32;
        for (int r=r0; r<CC; r+=4)
            X[r*PP + po + lane] = sh[r*33 + lane];
        __syncthreads();
    }
#pragma unroll
    for (int off=8; off; off>>=1){
        sum += __shfl_down_sync(0xffffffffu, sum, off, 16);
        sq  += __shfl_down_sync(0xffffffffu, sq,  off, 16);
    }
    if ((threadIdx.x & 15)==0){
        int g = c >> 4;
        atomicAdd(&stats[(b*GG+g)*2+0], sum);
        atomicAdd(&stats[(b*GG+g)*2+1], sq);
    }
}

// ---------------- fused GN+LReLU(load) -> f32x2 GEMM -> bias -> stats --------
// Y[o][p] = sum_c W[o][c] * lrelu(GN(X[c][p])) + bias[o]
__global__ void __launch_bounds__(256) k_gemm(const float* __restrict__ X,
        const float* __restrict__ WT, const float* __restrict__ bias,
        const float* __restrict__ statsIn, const float* __restrict__ gamma,
        const float* __restrict__ beta, float* __restrict__ Y,
        float* __restrict__ statsOut) {
    __shared__ float Ws[32*128];
    __shared__ float Xs[32*128];
    __shared__ float2 ssS[CC];
    int t = threadIdx.x;
    int pbase = blockIdx.x * 128;
    int b = pbase >> 16;
    if (t < CC) {
        int g = t >> 4;
        float s = statsIn[(b*GG+g)*2+0], q = statsIn[(b*GG+g)*2+1];
        float mu = s / CNTF;
        float var = q / CNTF - mu*mu;
        float rstd = rsqrtf(var + EPSF);
        float scale = rstd * gamma[t];
        ssS[t] = make_float2(scale, beta[t] - mu*scale);
    }

    unsigned long long acc[8][4];
#pragma unroll
    for (int i=0;i<8;i++)
#pragma unroll
        for (int j=0;j<4;j++) acc[i][j]=0ull;

    int tx = t & 15, ty = t >> 4;
    for (int kc=0; kc<CC; kc+=32) {
        __syncthreads();
#pragma unroll
        for (int l=t; l<4096; l+=256) {
            int k=l>>7, o=l&127;
            Ws[l] = WT[(kc+k)*CC + o];
        }
#pragma unroll
        for (int l=t; l<4096; l+=256) {
            int k=l>>7, p=l&127;
            float2 s = ssS[kc+k];
            float v = X[(kc+k)*PP + pbase + p]*s.x + s.y;
            Xs[l] = (v>=0.f) ? v : 0.1f*v;
        }
        __syncthreads();
#pragma unroll
        for (int k=0;k<32;k++){
            float4 a0 = *(const float4*)&Ws[k*128 + ty*4];
            float4 a1 = *(const float4*)&Ws[k*128 + 64 + ty*4];
            ulonglong2 b01 = *(const ulonglong2*)&Xs[k*128 + tx*4];
            ulonglong2 b23 = *(const ulonglong2*)&Xs[k*128 + 64 + tx*4];
            unsigned long long A[8];
            A[0]=bcast2(a0.x); A[1]=bcast2(a0.y); A[2]=bcast2(a0.z); A[3]=bcast2(a0.w);
            A[4]=bcast2(a1.x); A[5]=bcast2(a1.y); A[6]=bcast2(a1.z); A[7]=bcast2(a1.w);
            unsigned long long Bv[4] = {b01.x, b01.y, b23.x, b23.y};
#pragma unroll
            for (int i=0;i<8;i++)
#pragma unroll
                for (int j=0;j<4;j++) fma2(acc[i][j], A[i], Bv[j]);
        }
    }

    float s1=0.f,q1=0.f,s2=0.f,q2=0.f;
#pragma unroll
    for (int i=0;i<8;i++){
        int o = (i<4) ? (ty*4+i) : (64 + ty*4 + (i-4));
        float bv = bias[o];
        float y[8];
#pragma unroll
        for (int jp=0;jp<4;jp++){
            float2 f = unpk2(acc[i][jp]);
            y[2*jp]   = f.x + bv;
            y[2*jp+1] = f.y + bv;
        }
#pragma unroll
        for (int j=0;j<8;j++){
            if (i<4){ s1 += y[j]; q1 += y[j]*y[j]; }
            else    { s2 += y[j]; q2 += y[j]*y[j]; }
        }
        *(float4*)&Y[o*PP + pbase + tx*4]      = make_float4(y[0],y[1],y[2],y[3]);
        *(float4*)&Y[o*PP + pbase + 64 + tx*4] = make_float4(y[4],y[5],y[6],y[7]);
    }
#pragma unroll
    for (int off=16; off; off>>=1){
        s1 += __shfl_down_sync(0xffffffffu, s1, off);
        q1 += __shfl_down_sync(0xffffffffu, q1, off);
        s2 += __shfl_down_sync(0xffffffffu, s2, off);
        q2 += __shfl_down_sync(0xffffffffu, q2, off);
    }
    if ((t & 31)==0){
        int g1 = (t>>5)>>1;
        atomicAdd(&statsOut[(b*GG+g1)*2+0],   s1);
        atomicAdd(&statsOut[(b*GG+g1)*2+1],   q1);
        atomicAdd(&statsOut[(b*GG+4+g1)*2+0], s2);
        atomicAdd(&statsOut[(b*GG+4+g1)*2+1], q2);
    }
}

// ---------------- GN+LReLU apply + max-pool over K ---------------------------
__global__ void k_pool(const float* __restrict__ Y, const float* __restrict__ statsIn,
                       const float* __restrict__ gamma, const float* __restrict__ beta,
                       float* __restrict__ outPM, float* __restrict__ outCM) {
    int b = blockIdx.y, n0 = blockIdx.x*32, c = threadIdx.x;
    int g = c >> 4;
    float s = statsIn[(b*GG+g)*2+0], q = statsIn[(b*GG+g)*2+1];
    float mu = s / CNTF;
    float var = q / CNTF - mu*mu;
    float rstd = rsqrtf(var + EPSF);
    float scale = rstd * gamma[c];
    float shift = beta[c] - mu*scale;
    __shared__ float sh[CC*36];
    for (int nn=0; nn<32; nn++){
        const float4* yp = (const float4*)&Y[c*PP + b*PPB + (n0+nn)*KK];
        float mx = -1e30f;
#pragma unroll
        for (int qq=0;qq<4;qq++){
            float4 v4 = yp[qq];
            float vs[4] = {v4.x,v4.y,v4.z,v4.w};
#pragma unroll
            for (int u=0;u<4;u++){
                float v = vs[u]*scale + shift;
                v = (v>=0.f) ? v : 0.1f*v;
                mx = fmaxf(mx, v);
            }
        }
        if (outPM) outPM[(b*NN+n0+nn)*CC + c] = mx;
        sh[c*36+nn] = mx;
    }
    if (outCM){
        __syncthreads();
        int lane = threadIdx.x & 31, r0 = threadIdx.x >> 5;
        for (int r=r0; r<CC; r+=4)
            outCM[(b*CC+r)*NN + n0 + lane] = sh[r*36+lane];
    }
}

// ---------------- trailing 1x1 conv (t1 / t2) --------------------------------
__global__ void k_conv1d2(const float* __restrict__ pin, const float* __restrict__ w,
                          const float* __restrict__ bias, float* __restrict__ outCM,
                          float* __restrict__ fnT) {
    int b = blockIdx.y, n0 = blockIdx.x*32, o = threadIdx.x;
    __shared__ float xs[CC*36];
    for (int l=threadIdx.x; l<CC*32; l+=128){
        int nj = l>>7, c = l&127;
        xs[c*36+nj] = pin[(b*NN+n0+nj)*CC + c];
    }
    __syncthreads();
    float acc[32];
    float bv = bias[o];
#pragma unroll
    for (int j=0;j<32;j++) acc[j]=bv;
    for (int cc=0; cc<4; cc++){
        float wr[32];
#pragma unroll
        for (int c2=0;c2<32;c2++) wr[c2] = w[o*CC + cc*32 + c2];
#pragma unroll
        for (int c2=0;c2<32;c2++){
            const float* xrow = &xs[(cc*32+c2)*36];
            float wv = wr[c2];
#pragma unroll
            for (int j4=0;j4<8;j4++){
                float4 xv = *(const float4*)&xrow[j4*4];
                acc[j4*4+0]+=wv*xv.x; acc[j4*4+1]+=wv*xv.y;
                acc[j4*4+2]+=wv*xv.z; acc[j4*4+3]+=wv*xv.w;
            }
        }
    }
#pragma unroll
    for (int j=0;j<32;j++) fnT[(b*NN+n0+j)*CC + o] = acc[j];
    __syncthreads();
#pragma unroll
    for (int j=0;j<32;j++) xs[o*36+j] = acc[j];
    __syncthreads();
    int lane = threadIdx.x & 31, r0 = threadIdx.x >> 5;
    for (int r=r0; r<CC; r+=4)
        outCM[(b*CC+r)*NN + n0 + lane] = xs[r*36+lane];
}

// ---------------- host orchestration ----------------------------------------
extern "C" void kernel_launch(void* const* d_in, const int* in_sizes, int n_in,
                              void* d_out, int out_size) {
    const float* pc1     = (const float*)d_in[0];
    const float* pc2     = (const float*)d_in[1];
    const float* feat1   = (const float*)d_in[2];
    const float* feat2   = (const float*)d_in[3];
    const float* t11_w   = (const float*)d_in[4];
    const float* t11_b   = (const float*)d_in[5];
    const float* t22_w   = (const float*)d_in[6];
    const float* t22_b   = (const float*)d_in[7];
    const float* pos1_w  = (const float*)d_in[8];
    const float* pos1_b  = (const float*)d_in[9];
    const float* gn1_g   = (const float*)d_in[10];
    const float* gn1_b   = (const float*)d_in[11];
    const float* m1a_w   = (const float*)d_in[12];
    const float* m1a_b   = (const float*)d_in[13];
    const float* m1a_g   = (const float*)d_in[14];
    const float* m1a_beta= (const float*)d_in[15];
    const float* m1b_w   = (const float*)d_in[16];
    const float* m1b_b   = (const float*)d_in[17];
    const float* m1b_g   = (const float*)d_in[18];
    const float* m1b_beta= (const float*)d_in[19];
    const float* t1_w    = (const float*)d_in[20];
    const float* t1_b    = (const float*)d_in[21];
    const float* t2_w    = (const float*)d_in[22];
    const float* t2_b    = (const float*)d_in[23];
    const float* pos2_w  = (const float*)d_in[24];
    const float* pos2_b  = (const float*)d_in[25];
    const float* gn2_g   = (const float*)d_in[26];
    const float* gn2_b   = (const float*)d_in[27];
    const float* m2a_w   = (const float*)d_in[28];
    const float* m2a_b   = (const float*)d_in[29];
    const float* m2a_g   = (const float*)d_in[30];
    const float* m2a_beta= (const float*)d_in[31];
    float* out = (float*)d_out;

    float *f1T,*f2T,*g1T,*g2T,*fn1T,*fn2T,*bufA,*bufB,*poolb,*stats,*WT,*dir12,*dir21;
    int *idx12,*idx21;
    cudaGetSymbolAddress((void**)&f1T,  g_f1T);
    cudaGetSymbolAddress((void**)&f2T,  g_f2T);
    cudaGetSymbolAddress((void**)&g1T,  g_g1T);
    cudaGetSymbolAddress((void**)&g2T,  g_g2T);
    cudaGetSymbolAddress((void**)&fn1T, g_fn1T);
    cudaGetSymbolAddress((void**)&fn2T, g_fn2T);
    cudaGetSymbolAddress((void**)&idx12,g_idx12);
    cudaGetSymbolAddress((void**)&idx21,g_idx21);
    cudaGetSymbolAddress((void**)&dir12,g_dir12);
    cudaGetSymbolAddress((void**)&dir21,g_dir21);
    cudaGetSymbolAddress((void**)&bufA, g_bufA);
    cudaGetSymbolAddress((void**)&bufB, g_bufB);
    cudaGetSymbolAddress((void**)&poolb,g_pool);
    cudaGetSymbolAddress((void**)&stats,g_stats);
    cudaGetSymbolAddress((void**)&WT,   g_WT);

    const int STB = BB*GG*2;   // stats floats per stage

    cudaMemsetAsync(stats, 0, 8*STB*sizeof(float), 0);

    k_conv1d_in<<<dim3(NN/32, BB, 4), 128>>>(feat1, feat2, t11_w, t11_b, t22_w, t22_b);
    k_knn<<<dim3(NN/128, BB, 2), 512>>>(pc1, pc2);
    k_transw<<<3, 256>>>(m1a_w, m1b_w, m2a_w);

    // ---- cross 1: queries pc1, cands pc2, p1=f1, p2=f2 ----
    k_gather<<<dim3(NN/8, BB), 128>>>(idx12, dir12, f1T, f2T, pos1_w, pos1_b, bufA, stats+0*STB);
    k_gemm<<<PP/128, 256>>>(bufA, WT+0*CC*CC, m1a_b, stats+0*STB, gn1_g, gn1_b, bufB, stats+1*STB);
    k_gemm<<<PP/128, 256>>>(bufB, WT+1*CC*CC, m1b_b, stats+1*STB, m1a_g, m1a_beta, bufA, stats+2*STB);
    k_pool<<<dim3(NN/32, BB), 128>>>(bufA, stats+2*STB, m1b_g, m1b_beta, poolb, nullptr);
    k_conv1d2<<<dim3(NN/32, BB), 128>>>(poolb, t1_w, t1_b, out, fn1T);

    // ---- cross 2: queries pc2, cands pc1, p1=g1, p2=g2 ----
    k_gather<<<dim3(NN/8, BB), 128>>>(idx21, dir21, g1T, g2T, pos1_w, pos1_b, bufA, stats+3*STB);
    k_gemm<<<PP/128, 256>>>(bufA, WT+0*CC*CC, m1a_b, stats+3*STB, gn1_g, gn1_b, bufB, stats+4*STB);
    k_gemm<<<PP/128, 256>>>(bufB, WT+1*CC*CC, m1b_b, stats+4*STB, m1a_g, m1a_beta, bufA, stats+5*STB);
    k_pool<<<dim3(NN/32, BB), 128>>>(bufA, stats+5*STB, m1b_g, m1b_beta, poolb, nullptr);
    k_conv1d2<<<dim3(NN/32, BB), 128>>>(poolb, t2_w, t2_b, out + BB*CC*NN, fn2T);

    // ---- cross 3: queries pc1, cands pc2, p1=feat1_new, p2=feat2_new ----
    k_gather<<<dim3(NN/8, BB), 128>>>(idx12, dir12, fn1T, fn2T, pos2_w, pos2_b, bufA, stats+6*STB);
    k_gemm<<<PP/128, 256>>>(bufA, WT+2*CC*CC, m2a_b, stats+6*STB, gn2_g, gn2_b, bufB, stats+7*STB);
    k_pool<<<dim3(NN/32, BB), 128>>>(bufB, stats+7*STB, m2a_g, m2a_beta, nullptr, out + 2*BB*CC*NN);
}

// round 3
// speedup vs baseline: 1.0112x; 1.0112x over previous
#include <cuda_runtime.h>

#define BB 2
#define NN 4096
#define CC 128
#define CIN 64
#define KK 16
#define GG 8
#define PPB (NN*KK)       // 65536 positions per batch
#define PP (BB*PPB)       // 131072 total positions
#define EPSF 1e-5f
#define CNTF 1048576.0f   // 16 * 4096 * 16 elements per (b,g)

// ---------------- scratch (device globals; no allocs allowed) ----------------
__device__ float g_f1T[BB*NN*CC];
__device__ float g_f2T[BB*NN*CC];
__device__ float g_g1T[BB*NN*CC];
__device__ float g_g2T[BB*NN*CC];
__device__ float g_fn1T[BB*NN*CC];
__device__ float g_fn2T[BB*NN*CC];
__device__ int   g_idx12[BB*NN*KK];
__device__ int   g_idx21[BB*NN*KK];
__device__ float g_dir12[BB*NN*KK*3];
__device__ float g_dir21[BB*NN*KK*3];
__device__ float g_bufA[CC*PP];      // channel-major [c][p]
__device__ float g_bufB[CC*PP];
__device__ float g_pool[BB*NN*CC];   // position-major [b][n][c]
__device__ float g_stats[8*BB*GG*2]; // per-stage (sum, sumsq)
__device__ float g_WT[3*CC*CC];      // transposed mlp weights: WT[c][o]

// ---------------- input 1x1 convs: feat -> transposed features [b][n][c] ----
__global__ void k_conv1d_in(const float* __restrict__ feat1, const float* __restrict__ feat2,
                            const float* __restrict__ t11_w, const float* __restrict__ t11_b,
                            const float* __restrict__ t22_w, const float* __restrict__ t22_b) {
    int job = blockIdx.z;   // 0:f1=t11@feat1 1:f2=t22@feat2 2:g1=t11@feat2 3:g2=t22@feat1
    int b = blockIdx.y;
    int n0 = blockIdx.x * 32;
    const float* x    = (job==0||job==3) ? feat1 : feat2;
    const float* w    = (job==0||job==2) ? t11_w : t22_w;
    const float* bias = (job==0||job==2) ? t11_b : t22_b;
    float* outp = (job==0) ? g_f1T : (job==1) ? g_f2T : (job==2) ? g_g1T : g_g2T;

    __shared__ float xs[CIN*33];
    int t = threadIdx.x;   // 128
    for (int l=t; l<CIN*32; l+=128) {
        int c=l>>5, j=l&31;
        xs[c*33+j] = x[(b*CIN+c)*NN + n0+j];
    }
    __syncthreads();
    int o = t;
    float wr[CIN];
#pragma unroll
    for (int c=0;c<CIN;c++) wr[c] = w[o*CIN+c];
    float bv = bias[o];
    for (int j=0;j<32;j++){
        float acc = bv;
#pragma unroll
        for (int c=0;c<CIN;c++) acc += wr[c]*xs[c*33+j];
        outp[(b*NN+n0+j)*CC + o] = acc;
    }
}

// ---------------- KNN (k=16): 4-way candidate split + shuffle merge ----------
__global__ void __launch_bounds__(512) k_knn(const float* __restrict__ pc1, const float* __restrict__ pc2) {
    int dir = blockIdx.z;
    const float* pq   = (dir==0) ? pc1 : pc2;
    const float* pcnd = (dir==0) ? pc2 : pc1;
    int*   idxo = (dir==0) ? g_idx12 : g_idx21;
    float* diro = (dir==0) ? g_dir12 : g_dir21;
    int b = blockIdx.y;
    int t = threadIdx.x;
    int qi = t >> 2;        // query within block (0..127)
    int sl = t & 3;         // candidate slice (0..3)
    int n = blockIdx.x*128 + qi;

    float qx = pq[(b*3+0)*NN+n], qy = pq[(b*3+1)*NN+n], qz = pq[(b*3+2)*NN+n];
    float s1 = qx*qx + qy*qy + qz*qz;

    float bd[KK]; int bi[KK];
#pragma unroll
    for (int k=0;k<KK;k++){ bd[k]=1e30f; bi[k]=0; }
    float worst = 1e30f;

    __shared__ float4 sc[1024];
    for (int r=0; r<4; r++) {
        __syncthreads();
        for (int i=t; i<1024; i+=512) {
            int sl2 = i >> 8, ii = i & 255;
            int m = sl2*1024 + r*256 + ii;
            float x = pcnd[(b*3+0)*NN+m];
            float y = pcnd[(b*3+1)*NN+m];
            float z = pcnd[(b*3+2)*NN+m];
            sc[i] = make_float4(x,y,z, x*x+y*y+z*z);
        }
        __syncthreads();
        int mbase = sl*1024 + r*256;
        const float4* base = &sc[sl*256];
        for (int i=0;i<256;i++) {
            float4 c = base[i];
            float d = s1 + c.w - 2.f*(qx*c.x + qy*c.y + qz*c.z);
            if (d < worst) {
                int j = KK-1;
                while (j>0 && bd[j-1] > d) { bd[j]=bd[j-1]; bi[j]=bi[j-1]; j--; }
                bd[j]=d; bi[j]=mbase+i;
                worst = bd[KK-1];
            }
        }
    }
    const unsigned mask = 0xffffffffu;
#pragma unroll
    for (int off=1; off<=2; off<<=1) {
        float od[KK]; int oi[KK];
#pragma unroll
        for (int k=0;k<KK;k++){
            od[k] = __shfl_xor_sync(mask, bd[k], off);
            oi[k] = __shfl_xor_sync(mask, bi[k], off);
        }
        if ((sl & (2*off-1)) == 0) {
            for (int k=0;k<KK;k++){
                float d = od[k];
                if (d >= worst) break;
                int j = KK-1;
                while (j>0 && bd[j-1] > d) { bd[j]=bd[j-1]; bi[j]=bi[j-1]; j--; }
                bd[j]=d; bi[j]=oi[k];
                worst = bd[KK-1];
            }
        }
    }
    int lane = t & 31;
    int src = lane & ~3;
    int fbi[KK];
#pragma unroll
    for (int k=0;k<KK;k++) fbi[k] = __shfl_sync(mask, bi[k], src);
    for (int kk=0; kk<4; kk++){
        int k = sl*4 + kk;
        int m = fbi[k];
        idxo[(b*NN+n)*KK+k] = m;
        float dx = pcnd[(b*3+0)*NN+m] - qx;
        float dy = pcnd[(b*3+1)*NN+m] - qy;
        float dz = pcnd[(b*3+2)*NN+m] - qz;
        diro[((b*NN+n)*KK+k)*3+0] = dx;
        diro[((b*NN+n)*KK+k)*3+1] = dy;
        diro[((b*NN+n)*KK+k)*3+2] = dz;
    }
}

// -------- weight transpose (m1a, m1b, m2a) + stats zeroing (replaces memset) --
__global__ void k_transw(const float* __restrict__ m1a, const float* __restrict__ m1b,
                         const float* __restrict__ m2a, float* __restrict__ stats) {
    if (blockIdx.x == 0) {
        for (int l=threadIdx.x; l<8*BB*GG*2; l+=256) stats[l] = 0.f;
    }
    const float* src = (blockIdx.x==0) ? m1a : (blockIdx.x==1) ? m1b : m2a;
    float* dst = g_WT + blockIdx.x*CC*CC;
    for (int l=threadIdx.x; l<CC*CC; l+=256){
        int o=l>>7, c=l&127;
        dst[c*CC+o] = src[l];
    }
}

// ---------------- gather prologue of a cross block ---------------------------
__global__ void k_gather(const int* __restrict__ idx, const float* __restrict__ dirv,
                         const float* __restrict__ p1T, const float* __restrict__ p2T,
                         const float* __restrict__ pos_w, const float* __restrict__ pos_b,
                         float* __restrict__ X, float* __restrict__ stats) {
    int b = blockIdx.y, n0 = blockIdx.x*8, c = threadIdx.x;
    float pw0 = pos_w[c*3+0], pw1 = pos_w[c*3+1], pw2 = pos_w[c*3+2], pb = pos_b[c];
    __shared__ float sh[CC*33];
    float sum=0.f, sq=0.f;
    int pbase = b*PPB + n0*KK;
    int lane = threadIdx.x & 31, r0 = threadIdx.x >> 5;

    for (int half=0; half<4; half++){
        for (int nn=0; nn<2; nn++){
            int n = n0 + half*2 + nn;
            float p1v = p1T[(b*NN+n)*CC + c];
            const int* ip = &idx[(b*NN+n)*KK];
            const float* dp0 = &dirv[(b*NN+n)*KK*3];
            for (int k=0;k<KK;k++){
                int m = ip[k];
                float pf = pw0*dp0[k*3+0] + pw1*dp0[k*3+1] + pw2*dp0[k*3+2] + pb;
                float v = p2T[(b*NN+m)*CC + c] + p1v + pf;
                sum += v; sq += v*v;
                sh[c*33 + nn*KK + k] = v;
            }
        }
        __syncthreads();
        int po = pbase + half*32;
        for (int r=r0; r<CC; r+=4)
            X[r*PP + po + lane] = sh[r*33 + lane];
        __syncthreads();
    }
#pragma unroll
    for (int off=8; off; off>>=1){
        sum += __shfl_down_sync(0xffffffffu, sum, off, 16);
        sq  += __shfl_down_sync(0xffffffffu, sq,  off, 16);
    }
    if ((threadIdx.x & 15)==0){
        int g = c >> 4;
        atomicAdd(&stats[(b*GG+g)*2+0], sum);
        atomicAdd(&stats[(b*GG+g)*2+1], sq);
    }
}

// ---- fused GN+LReLU(load) -> scalar GEMM (double-buffered) -> bias -> stats --
// Y[o][p] = sum_c W[o][c] * lrelu(GN(X[c][p])) + bias[o]
__global__ void __launch_bounds__(256) k_gemm(const float* __restrict__ X,
        const float* __restrict__ WT, const float* __restrict__ bias,
        const float* __restrict__ statsIn, const float* __restrict__ gamma,
        const float* __restrict__ beta, float* __restrict__ Y,
        float* __restrict__ statsOut) {
    __shared__ float Ws[2][16*128];
    __shared__ float Xs[2][16*128];
    __shared__ float2 ssS[CC];
    int t = threadIdx.x;
    int pbase = blockIdx.x * 128;
    int b = pbase >> 16;
    if (t < CC) {
        int g = t >> 4;
        float s = statsIn[(b*GG+g)*2+0], q = statsIn[(b*GG+g)*2+1];
        float mu = s / CNTF;
        float var = q / CNTF - mu*mu;
        float rstd = rsqrtf(var + EPSF);
        float scale = rstd * gamma[t];
        ssS[t] = make_float2(scale, beta[t] - mu*scale);
    }
    __syncthreads();

    float wreg[8], xreg[8];
    // stage chunk 0
#pragma unroll
    for (int i=0;i<8;i++){
        int l = t + i*256; int k = l>>7, p = l&127;
        wreg[i] = WT[k*CC + p];
        float2 s = ssS[k];
        float v = X[k*PP + pbase + p]*s.x + s.y;
        xreg[i] = (v>=0.f) ? v : 0.1f*v;
    }
#pragma unroll
    for (int i=0;i<8;i++){
        int l = t + i*256;
        Ws[0][l] = wreg[i];
        Xs[0][l] = xreg[i];
    }
    __syncthreads();

    float acc[8][8];
#pragma unroll
    for (int i=0;i<8;i++)
#pragma unroll
        for (int j=0;j<8;j++) acc[i][j]=0.f;

    int tx = t & 15, ty = t >> 4;
    for (int ch=0; ch<8; ch++) {
        int cur = ch & 1;
        if (ch < 7) {
            int kb = (ch+1)*16;
#pragma unroll
            for (int i=0;i<8;i++){
                int l = t + i*256; int k = l>>7, p = l&127;
                wreg[i] = WT[(kb+k)*CC + p];
                float2 s = ssS[kb+k];
                float v = X[(kb+k)*PP + pbase + p]*s.x + s.y;
                xreg[i] = (v>=0.f) ? v : 0.1f*v;
            }
        }
#pragma unroll
        for (int k=0;k<16;k++){
            float4 a0 = *(const float4*)&Ws[cur][k*128 + ty*4];
            float4 a1 = *(const float4*)&Ws[cur][k*128 + 64 + ty*4];
            float4 b0 = *(const float4*)&Xs[cur][k*128 + tx*4];
            float4 b1 = *(const float4*)&Xs[cur][k*128 + 64 + tx*4];
            float av[8] = {a0.x,a0.y,a0.z,a0.w,a1.x,a1.y,a1.z,a1.w};
            float bv[8] = {b0.x,b0.y,b0.z,b0.w,b1.x,b1.y,b1.z,b1.w};
#pragma unroll
            for (int i=0;i<8;i++)
#pragma unroll
                for (int j=0;j<8;j++) acc[i][j] += av[i]*bv[j];
        }
        if (ch < 7) {
#pragma unroll
            for (int i=0;i<8;i++){
                int l = t + i*256;
                Ws[1-cur][l] = wreg[i];
                Xs[1-cur][l] = xreg[i];
            }
        }
        __syncthreads();
    }

    float s1=0.f,q1=0.f,s2=0.f,q2=0.f;
#pragma unroll
    for (int i=0;i<8;i++){
        int o = (i<4) ? (ty*4+i) : (64 + ty*4 + (i-4));
        float bv = bias[o];
        float y[8];
#pragma unroll
        for (int j=0;j<8;j++){
            y[j] = acc[i][j] + bv;
            if (i<4){ s1 += y[j]; q1 += y[j]*y[j]; }
            else    { s2 += y[j]; q2 += y[j]*y[j]; }
        }
        *(float4*)&Y[o*PP + pbase + tx*4]      = make_float4(y[0],y[1],y[2],y[3]);
        *(float4*)&Y[o*PP + pbase + 64 + tx*4] = make_float4(y[4],y[5],y[6],y[7]);
    }
#pragma unroll
    for (int off=16; off; off>>=1){
        s1 += __shfl_down_sync(0xffffffffu, s1, off);
        q1 += __shfl_down_sync(0xffffffffu, q1, off);
        s2 += __shfl_down_sync(0xffffffffu, s2, off);
        q2 += __shfl_down_sync(0xffffffffu, q2, off);
    }
    if ((t & 31)==0){
        int g1 = (t>>5)>>1;
        atomicAdd(&statsOut[(b*GG+g1)*2+0],   s1);
        atomicAdd(&statsOut[(b*GG+g1)*2+1],   q1);
        atomicAdd(&statsOut[(b*GG+4+g1)*2+0], s2);
        atomicAdd(&statsOut[(b*GG+4+g1)*2+1], q2);
    }
}

// ---------------- GN+LReLU apply + max-pool over K ---------------------------
__global__ void k_pool(const float* __restrict__ Y, const float* __restrict__ statsIn,
                       const float* __restrict__ gamma, const float* __restrict__ beta,
                       float* __restrict__ outPM, float* __restrict__ outCM) {
    int b = blockIdx.y, n0 = blockIdx.x*32, c = threadIdx.x;
    int g = c >> 4;
    float s = statsIn[(b*GG+g)*2+0], q = statsIn[(b*GG+g)*2+1];
    float mu = s / CNTF;
    float var = q / CNTF - mu*mu;
    float rstd = rsqrtf(var + EPSF);
    float scale = rstd * gamma[c];
    float shift = beta[c] - mu*scale;
    __shared__ float sh[CC*36];
    for (int nn=0; nn<32; nn++){
        const float4* yp = (const float4*)&Y[c*PP + b*PPB + (n0+nn)*KK];
        float mx = -1e30f;
#pragma unroll
        for (int qq=0;qq<4;qq++){
            float4 v4 = yp[qq];
            float vs[4] = {v4.x,v4.y,v4.z,v4.w};
#pragma unroll
            for (int u=0;u<4;u++){
                float v = vs[u]*scale + shift;
                v = (v>=0.f) ? v : 0.1f*v;
                mx = fmaxf(mx, v);
            }
        }
        if (outPM) outPM[(b*NN+n0+nn)*CC + c] = mx;
        sh[c*36+nn] = mx;
    }
    if (outCM){
        __syncthreads();
        int lane = threadIdx.x & 31, r0 = threadIdx.x >> 5;
        for (int r=r0; r<CC; r+=4)
            outCM[(b*CC+r)*NN + n0 + lane] = sh[r*36+lane];
    }
}

// ---------------- trailing 1x1 conv (t1 / t2) --------------------------------
__global__ void k_conv1d2(const float* __restrict__ pin, const float* __restrict__ w,
                          const float* __restrict__ bias, float* __restrict__ outCM,
                          float* __restrict__ fnT) {
    int b = blockIdx.y, n0 = blockIdx.x*32, o = threadIdx.x;
    __shared__ float xs[CC*36];
    for (int l=threadIdx.x; l<CC*32; l+=128){
        int nj = l>>7, c = l&127;
        xs[c*36+nj] = pin[(b*NN+n0+nj)*CC + c];
    }
    __syncthreads();
    float acc[32];
    float bv = bias[o];
#pragma unroll
    for (int j=0;j<32;j++) acc[j]=bv;
    for (int cc=0; cc<4; cc++){
        float wr[32];
#pragma unroll
        for (int c2=0;c2<32;c2++) wr[c2] = w[o*CC + cc*32 + c2];
#pragma unroll
        for (int c2=0;c2<32;c2++){
            const float* xrow = &xs[(cc*32+c2)*36];
            float wv = wr[c2];
#pragma unroll
            for (int j4=0;j4<8;j4++){
                float4 xv = *(const float4*)&xrow[j4*4];
                acc[j4*4+0]+=wv*xv.x; acc[j4*4+1]+=wv*xv.y;
                acc[j4*4+2]+=wv*xv.z; acc[j4*4+3]+=wv*xv.w;
            }
        }
    }
#pragma unroll
    for (int j=0;j<32;j++) fnT[(b*NN+n0+j)*CC + o] = acc[j];
    __syncthreads();
#pragma unroll
    for (int j=0;j<32;j++) xs[o*36+j] = acc[j];
    __syncthreads();
    int lane = threadIdx.x & 31, r0 = threadIdx.x >> 5;
    for (int r=r0; r<CC; r+=4)
        outCM[(b*CC+r)*NN + n0 + lane] = xs[r*36+lane];
}

// ---------------- host orchestration ----------------------------------------
extern "C" void kernel_launch(void* const* d_in, const int* in_sizes, int n_in,
                              void* d_out, int out_size) {
    const float* pc1     = (const float*)d_in[0];
    const float* pc2     = (const float*)d_in[1];
    const float* feat1   = (const float*)d_in[2];
    const float* feat2   = (const float*)d_in[3];
    const float* t11_w   = (const float*)d_in[4];
    const float* t11_b   = (const float*)d_in[5];
    const float* t22_w   = (const float*)d_in[6];
    const float* t22_b   = (const float*)d_in[7];
    const float* pos1_w  = (const float*)d_in[8];
    const float* pos1_b  = (const float*)d_in[9];
    const float* gn1_g   = (const float*)d_in[10];
    const float* gn1_b   = (const float*)d_in[11];
    const float* m1a_w   = (const float*)d_in[12];
    const float* m1a_b   = (const float*)d_in[13];
    const float* m1a_g   = (const float*)d_in[14];
    const float* m1a_beta= (const float*)d_in[15];
    const float* m1b_w   = (const float*)d_in[16];
    const float* m1b_b   = (const float*)d_in[17];
    const float* m1b_g   = (const float*)d_in[18];
    const float* m1b_beta= (const float*)d_in[19];
    const float* t1_w    = (const float*)d_in[20];
    const float* t1_b    = (const float*)d_in[21];
    const float* t2_w    = (const float*)d_in[22];
    const float* t2_b    = (const float*)d_in[23];
    const float* pos2_w  = (const float*)d_in[24];
    const float* pos2_b  = (const float*)d_in[25];
    const float* gn2_g   = (const float*)d_in[26];
    const float* gn2_b   = (const float*)d_in[27];
    const float* m2a_w   = (const float*)d_in[28];
    const float* m2a_b   = (const float*)d_in[29];
    const float* m2a_g   = (const float*)d_in[30];
    const float* m2a_beta= (const float*)d_in[31];
    float* out = (float*)d_out;

    float *f1T,*f2T,*g1T,*g2T,*fn1T,*fn2T,*bufA,*bufB,*poolb,*stats,*WT,*dir12,*dir21;
    int *idx12,*idx21;
    cudaGetSymbolAddress((void**)&f1T,  g_f1T);
    cudaGetSymbolAddress((void**)&f2T,  g_f2T);
    cudaGetSymbolAddress((void**)&g1T,  g_g1T);
    cudaGetSymbolAddress((void**)&g2T,  g_g2T);
    cudaGetSymbolAddress((void**)&fn1T, g_fn1T);
    cudaGetSymbolAddress((void**)&fn2T, g_fn2T);
    cudaGetSymbolAddress((void**)&idx12,g_idx12);
    cudaGetSymbolAddress((void**)&idx21,g_idx21);
    cudaGetSymbolAddress((void**)&dir12,g_dir12);
    cudaGetSymbolAddress((void**)&dir21,g_dir21);
    cudaGetSymbolAddress((void**)&bufA, g_bufA);
    cudaGetSymbolAddress((void**)&bufB, g_bufB);
    cudaGetSymbolAddress((void**)&poolb,g_pool);
    cudaGetSymbolAddress((void**)&stats,g_stats);
    cudaGetSymbolAddress((void**)&WT,   g_WT);

    const int STB = BB*GG*2;   // stats floats per stage

    k_conv1d_in<<<dim3(NN/32, BB, 4), 128>>>(feat1, feat2, t11_w, t11_b, t22_w, t22_b);
    k_knn<<<dim3(NN/128, BB, 2), 512>>>(pc1, pc2);
    k_transw<<<3, 256>>>(m1a_w, m1b_w, m2a_w, stats);

    // ---- cross 1: queries pc1, cands pc2, p1=f1, p2=f2 ----
    k_gather<<<dim3(NN/8, BB), 128>>>(idx12, dir12, f1T, f2T, pos1_w, pos1_b, bufA, stats+0*STB);
    k_gemm<<<PP/128, 256>>>(bufA, WT+0*CC*CC, m1a_b, stats+0*STB, gn1_g, gn1_b, bufB, stats+1*STB);
    k_gemm<<<PP/128, 256>>>(bufB, WT+1*CC*CC, m1b_b, stats+1*STB, m1a_g, m1a_beta, bufA, stats+2*STB);
    k_pool<<<dim3(NN/32, BB), 128>>>(bufA, stats+2*STB, m1b_g, m1b_beta, poolb, nullptr);
    k_conv1d2<<<dim3(NN/32, BB), 128>>>(poolb, t1_w, t1_b, out, fn1T);

    // ---- cross 2: queries pc2, cands pc1, p1=g1, p2=g2 ----
    k_gather<<<dim3(NN/8, BB), 128>>>(idx21, dir21, g1T, g2T, pos1_w, pos1_b, bufA, stats+3*STB);
    k_gemm<<<PP/128, 256>>>(bufA, WT+0*CC*CC, m1a_b, stats+3*STB, gn1_g, gn1_b, bufB, stats+4*STB);
    k_gemm<<<PP/128, 256>>>(bufB, WT+1*CC*CC, m1b_b, stats+4*STB, m1a_g, m1a_beta, bufA, stats+5*STB);
    k_pool<<<dim3(NN/32, BB), 128>>>(bufA, stats+5*STB, m1b_g, m1b_beta, poolb, nullptr);
    k_conv1d2<<<dim3(NN/32, BB), 128>>>(poolb, t2_w, t2_b, out + BB*CC*NN, fn2T);

    // ---- cross 3: queries pc1, cands pc2, p1=feat1_new, p2=feat2_new ----
    k_gather<<<dim3(NN/8, BB), 128>>>(idx12, dir12, fn1T, fn2T, pos2_w, pos2_b, bufA, stats+6*STB);
    k_gemm<<<PP/128, 256>>>(bufA, WT+2*CC*CC, m2a_b, stats+6*STB, gn2_g, gn2_b, bufB, stats+7*STB);
    k_pool<<<dim3(NN/32, BB), 128>>>(bufB, stats+7*STB, m2a_g, m2a_beta, nullptr, out + 2*BB*CC*NN);
}

// round 4
// speedup vs baseline: 1.2940x; 1.2796x over previous
#include <cuda_runtime.h>

#define BB 2
#define NN 4096
#define CC 128
#define CIN 64
#define KK 16
#define GG 8
#define PPB (NN*KK)       // 65536 positions per batch
#define PP (BB*PPB)       // 131072 total positions
#define EPSF 1e-5f
#define CNTF 1048576.0f   // 16 * 4096 * 16 elements per (b,g)

// ---------------- scratch (device globals; no allocs allowed) ----------------
__device__ float g_f1T[BB*NN*CC];
__device__ float g_f2T[BB*NN*CC];
__device__ float g_g1T[BB*NN*CC];
__device__ float g_g2T[BB*NN*CC];
__device__ float g_fn1T[BB*NN*CC];
__device__ float g_fn2T[BB*NN*CC];
__device__ int   g_idx12[BB*NN*KK];
__device__ int   g_idx21[BB*NN*KK];
__device__ float g_dir12[BB*NN*KK*3];
__device__ float g_dir21[BB*NN*KK*3];
__device__ float g_bufA[CC*PP];      // channel-major [c][p]
__device__ float g_bufB[CC*PP];
__device__ float g_pool[BB*NN*CC];   // position-major [b][n][c]
__device__ float g_stats[8*BB*GG*2]; // per-stage (sum, sumsq)
__device__ float g_WT[3*CC*CC];      // transposed mlp weights: WT[c][o]

// ---------------- input 1x1 convs: feat -> transposed features [b][n][c] ----
__global__ void k_conv1d_in(const float* __restrict__ feat1, const float* __restrict__ feat2,
                            const float* __restrict__ t11_w, const float* __restrict__ t11_b,
                            const float* __restrict__ t22_w, const float* __restrict__ t22_b) {
    int job = blockIdx.z;   // 0:f1=t11@feat1 1:f2=t22@feat2 2:g1=t11@feat2 3:g2=t22@feat1
    int b = blockIdx.y;
    int n0 = blockIdx.x * 32;
    const float* x    = (job==0||job==3) ? feat1 : feat2;
    const float* w    = (job==0||job==2) ? t11_w : t22_w;
    const float* bias = (job==0||job==2) ? t11_b : t22_b;
    float* outp = (job==0) ? g_f1T : (job==1) ? g_f2T : (job==2) ? g_g1T : g_g2T;

    __shared__ float xs[CIN*33];
    int t = threadIdx.x;   // 128
    for (int l=t; l<CIN*32; l+=128) {
        int c=l>>5, j=l&31;
        xs[c*33+j] = x[(b*CIN+c)*NN + n0+j];
    }
    __syncthreads();
    int o = t;
    float wr[CIN];
#pragma unroll
    for (int c=0;c<CIN;c++) wr[c] = w[o*CIN+c];
    float bv = bias[o];
    for (int j=0;j<32;j++){
        float acc = bv;
#pragma unroll
        for (int c=0;c<CIN;c++) acc += wr[c]*xs[c*33+j];
        outp[(b*NN+n0+j)*CC + o] = acc;
    }
}

// ---------------- KNN (k=16), R1 broadcast version ---------------------------
__global__ void k_knn(const float* __restrict__ pc1, const float* __restrict__ pc2) {
    int dir = blockIdx.z;
    const float* pq   = (dir==0) ? pc1 : pc2;
    const float* pcnd = (dir==0) ? pc2 : pc1;
    int*   idxo = (dir==0) ? g_idx12 : g_idx21;
    float* diro = (dir==0) ? g_dir12 : g_dir21;
    int b = blockIdx.y;
    int n = blockIdx.x*128 + threadIdx.x;

    float qx = pq[(b*3+0)*NN+n], qy = pq[(b*3+1)*NN+n], qz = pq[(b*3+2)*NN+n];
    float s1 = qx*qx + qy*qy + qz*qz;

    float bd[KK]; int bi[KK];
#pragma unroll
    for (int k=0;k<KK;k++){ bd[k]=1e30f; bi[k]=0; }
    float worst = 1e30f;

    __shared__ float4 sc[512];
    for (int m0=0; m0<NN; m0+=512) {
        __syncthreads();
        for (int i=threadIdx.x; i<512; i+=128) {
            float x = pcnd[(b*3+0)*NN+m0+i];
            float y = pcnd[(b*3+1)*NN+m0+i];
            float z = pcnd[(b*3+2)*NN+m0+i];
            sc[i] = make_float4(x,y,z, x*x+y*y+z*z);
        }
        __syncthreads();
        for (int i=0;i<512;i++) {
            float4 c = sc[i];
            float d = s1 + c.w - 2.f*(qx*c.x + qy*c.y + qz*c.z);
            if (d < worst) {
                int j = KK-1;
                while (j>0 && bd[j-1] > d) { bd[j]=bd[j-1]; bi[j]=bi[j-1]; j--; }
                bd[j]=d; bi[j]=m0+i;
                worst = bd[KK-1];
            }
        }
    }
    for (int k=0;k<KK;k++){
        int m = bi[k];
        idxo[(b*NN+n)*KK+k] = m;
        float dx = pcnd[(b*3+0)*NN+m] - qx;
        float dy = pcnd[(b*3+1)*NN+m] - qy;
        float dz = pcnd[(b*3+2)*NN+m] - qz;
        diro[((b*NN+n)*KK+k)*3+0] = dx;
        diro[((b*NN+n)*KK+k)*3+1] = dy;
        diro[((b*NN+n)*KK+k)*3+2] = dz;
    }
}

// -------- weight transpose (m1a, m1b, m2a) + stats zeroing (replaces memset) --
__global__ void k_transw(const float* __restrict__ m1a, const float* __restrict__ m1b,
                         const float* __restrict__ m2a, float* __restrict__ stats) {
    if (blockIdx.x == 0) {
        for (int l=threadIdx.x; l<8*BB*GG*2; l+=256) stats[l] = 0.f;
    }
    const float* src = (blockIdx.x==0) ? m1a : (blockIdx.x==1) ? m1b : m2a;
    float* dst = g_WT + blockIdx.x*CC*CC;
    for (int l=threadIdx.x; l<CC*CC; l+=256){
        int o=l>>7, c=l&127;
        dst[c*CC+o] = src[l];
    }
}

// ---------------- gather prologue of a cross block ---------------------------
__global__ void k_gather(const int* __restrict__ idx, const float* __restrict__ dirv,
                         const float* __restrict__ p1T, const float* __restrict__ p2T,
                         const float* __restrict__ pos_w, const float* __restrict__ pos_b,
                         float* __restrict__ X, float* __restrict__ stats) {
    int b = blockIdx.y, n0 = blockIdx.x*8, c = threadIdx.x;
    float pw0 = pos_w[c*3+0], pw1 = pos_w[c*3+1], pw2 = pos_w[c*3+2], pb = pos_b[c];
    __shared__ float sh[CC*33];
    float sum=0.f, sq=0.f;
    int pbase = b*PPB + n0*KK;
    int lane = threadIdx.x & 31, r0 = threadIdx.x >> 5;

    for (int half=0; half<4; half++){
        for (int nn=0; nn<2; nn++){
            int n = n0 + half*2 + nn;
            float p1v = p1T[(b*NN+n)*CC + c];
            const int* ip = &idx[(b*NN+n)*KK];
            const float* dp0 = &dirv[(b*NN+n)*KK*3];
            for (int k=0;k<KK;k++){
                int m = ip[k];
                float pf = pw0*dp0[k*3+0] + pw1*dp0[k*3+1] + pw2*dp0[k*3+2] + pb;
                float v = p2T[(b*NN+m)*CC + c] + p1v + pf;
                sum += v; sq += v*v;
                sh[c*33 + nn*KK + k] = v;
            }
        }
        __syncthreads();
        int po = pbase + half*32;
        for (int r=r0; r<CC; r+=4)
            X[r*PP + po + lane] = sh[r*33 + lane];
        __syncthreads();
    }
#pragma unroll
    for (int off=8; off; off>>=1){
        sum += __shfl_down_sync(0xffffffffu, sum, off, 16);
        sq  += __shfl_down_sync(0xffffffffu, sq,  off, 16);
    }
    if ((threadIdx.x & 15)==0){
        int g = c >> 4;
        atomicAdd(&stats[(b*GG+g)*2+0], sum);
        atomicAdd(&stats[(b*GG+g)*2+1], sq);
    }
}

// ---- fused GN+LReLU(load) -> scalar GEMM (R1 structure) -> bias -> stats ----
// Y[o][p] = sum_c W[o][c] * lrelu(GN(X[c][p])) + bias[o]
__global__ void __launch_bounds__(256) k_gemm(const float* __restrict__ X,
        const float* __restrict__ WT, const float* __restrict__ bias,
        const float* __restrict__ statsIn, const float* __restrict__ gamma,
        const float* __restrict__ beta, float* __restrict__ Y,
        float* __restrict__ statsOut) {
    __shared__ float Ws[32*128];
    __shared__ float Xs[32*128];
    __shared__ float2 ssS[CC];
    int t = threadIdx.x;
    int pbase = blockIdx.x * 128;
    int b = pbase >> 16;
    if (t < CC) {
        int g = t >> 4;
        float s = statsIn[(b*GG+g)*2+0], q = statsIn[(b*GG+g)*2+1];
        float mu = s / CNTF;
        float var = q / CNTF - mu*mu;
        float rstd = rsqrtf(var + EPSF);
        float scale = rstd * gamma[t];
        ssS[t] = make_float2(scale, beta[t] - mu*scale);
    }

    float acc[8][8];
#pragma unroll
    for (int i=0;i<8;i++)
#pragma unroll
        for (int j=0;j<8;j++) acc[i][j]=0.f;

    int tx = t & 15, ty = t >> 4;
    for (int kc=0; kc<CC; kc+=32) {
        __syncthreads();
#pragma unroll
        for (int l=t; l<4096; l+=256) {
            int k=l>>7, o=l&127;
            Ws[l] = WT[(kc+k)*CC + o];
        }
#pragma unroll
        for (int l=t; l<4096; l+=256) {
            int k=l>>7, p=l&127;
            float2 s = ssS[kc+k];
            float v = X[(kc+k)*PP + pbase + p]*s.x + s.y;
            Xs[l] = (v>=0.f) ? v : 0.1f*v;
        }
        __syncthreads();
#pragma unroll
        for (int k=0;k<32;k++){
            float4 a0 = *(const float4*)&Ws[k*128 + ty*4];
            float4 a1 = *(const float4*)&Ws[k*128 + 64 + ty*4];
            float4 b0 = *(const float4*)&Xs[k*128 + tx*4];
            float4 b1 = *(const float4*)&Xs[k*128 + 64 + tx*4];
            float av[8] = {a0.x,a0.y,a0.z,a0.w,a1.x,a1.y,a1.z,a1.w};
            float bv[8] = {b0.x,b0.y,b0.z,b0.w,b1.x,b1.y,b1.z,b1.w};
#pragma unroll
            for (int i=0;i<8;i++)
#pragma unroll
                for (int j=0;j<8;j++) acc[i][j] += av[i]*bv[j];
        }
    }

    float s1=0.f,q1=0.f,s2=0.f,q2=0.f;
#pragma unroll
    for (int i=0;i<8;i++){
        int o = (i<4) ? (ty*4+i) : (64 + ty*4 + (i-4));
        float bv = bias[o];
        float y[8];
#pragma unroll
        for (int j=0;j<8;j++){
            y[j] = acc[i][j] + bv;
            if (i<4){ s1 += y[j]; q1 += y[j]*y[j]; }
            else    { s2 += y[j]; q2 += y[j]*y[j]; }
        }
        *(float4*)&Y[o*PP + pbase + tx*4]      = make_float4(y[0],y[1],y[2],y[3]);
        *(float4*)&Y[o*PP + pbase + 64 + tx*4] = make_float4(y[4],y[5],y[6],y[7]);
    }
#pragma unroll
    for (int off=16; off; off>>=1){
        s1 += __shfl_down_sync(0xffffffffu, s1, off);
        q1 += __shfl_down_sync(0xffffffffu, q1, off);
        s2 += __shfl_down_sync(0xffffffffu, s2, off);
        q2 += __shfl_down_sync(0xffffffffu, q2, off);
    }
    if ((t & 31)==0){
        int g1 = (t>>5)>>1;
        atomicAdd(&statsOut[(b*GG+g1)*2+0],   s1);
        atomicAdd(&statsOut[(b*GG+g1)*2+1],   q1);
        atomicAdd(&statsOut[(b*GG+4+g1)*2+0], s2);
        atomicAdd(&statsOut[(b*GG+4+g1)*2+1], q2);
    }
}

// ---------------- GN+LReLU apply + max-pool over K ---------------------------
__global__ void k_pool(const float* __restrict__ Y, const float* __restrict__ statsIn,
                       const float* __restrict__ gamma, const float* __restrict__ beta,
                       float* __restrict__ outPM, float* __restrict__ outCM) {
    int b = blockIdx.y, n0 = blockIdx.x*32, c = threadIdx.x;
    int g = c >> 4;
    float s = statsIn[(b*GG+g)*2+0], q = statsIn[(b*GG+g)*2+1];
    float mu = s / CNTF;
    float var = q / CNTF - mu*mu;
    float rstd = rsqrtf(var + EPSF);
    float scale = rstd * gamma[c];
    float shift = beta[c] - mu*scale;
    __shared__ float sh[CC*36];
    for (int nn=0; nn<32; nn++){
        const float4* yp = (const float4*)&Y[c*PP + b*PPB + (n0+nn)*KK];
        float mx = -1e30f;
#pragma unroll
        for (int qq=0;qq<4;qq++){
            float4 v4 = yp[qq];
            float vs[4] = {v4.x,v4.y,v4.z,v4.w};
#pragma unroll
            for (int u=0;u<4;u++){
                float v = vs[u]*scale + shift;
                v = (v>=0.f) ? v : 0.1f*v;
                mx = fmaxf(mx, v);
            }
        }
        if (outPM) outPM[(b*NN+n0+nn)*CC + c] = mx;
        sh[c*36+nn] = mx;
    }
    if (outCM){
        __syncthreads();
        int lane = threadIdx.x & 31, r0 = threadIdx.x >> 5;
        for (int r=r0; r<CC; r+=4)
            outCM[(b*CC+r)*NN + n0 + lane] = sh[r*36+lane];
    }
}

// ---------------- trailing 1x1 conv (t1 / t2) --------------------------------
__global__ void k_conv1d2(const float* __restrict__ pin, const float* __restrict__ w,
                          const float* __restrict__ bias, float* __restrict__ outCM,
                          float* __restrict__ fnT) {
    int b = blockIdx.y, n0 = blockIdx.x*32, o = threadIdx.x;
    __shared__ float xs[CC*36];
    for (int l=threadIdx.x; l<CC*32; l+=128){
        int nj = l>>7, c = l&127;
        xs[c*36+nj] = pin[(b*NN+n0+nj)*CC + c];
    }
    __syncthreads();
    float acc[32];
    float bv = bias[o];
#pragma unroll
    for (int j=0;j<32;j++) acc[j]=bv;
    for (int cc=0; cc<4; cc++){
        float wr[32];
#pragma unroll
        for (int c2=0;c2<32;c2++) wr[c2] = w[o*CC + cc*32 + c2];
#pragma unroll
        for (int c2=0;c2<32;c2++){
            const float* xrow = &xs[(cc*32+c2)*36];
            float wv = wr[c2];
#pragma unroll
            for (int j4=0;j4<8;j4++){
                float4 xv = *(const float4*)&xrow[j4*4];
                acc[j4*4+0]+=wv*xv.x; acc[j4*4+1]+=wv*xv.y;
                acc[j4*4+2]+=wv*xv.z; acc[j4*4+3]+=wv*xv.w;
            }
        }
    }
#pragma unroll
    for (int j=0;j<32;j++) fnT[(b*NN+n0+j)*CC + o] = acc[j];
    __syncthreads();
#pragma unroll
    for (int j=0;j<32;j++) xs[o*36+j] = acc[j];
    __syncthreads();
    int lane = threadIdx.x & 31, r0 = threadIdx.x >> 5;
    for (int r=r0; r<CC; r+=4)
        outCM[(b*CC+r)*NN + n0 + lane] = xs[r*36+lane];
}

// ---------------- host orchestration ----------------------------------------
extern "C" void kernel_launch(void* const* d_in, const int* in_sizes, int n_in,
                              void* d_out, int out_size) {
    const float* pc1     = (const float*)d_in[0];
    const float* pc2     = (const float*)d_in[1];
    const float* feat1   = (const float*)d_in[2];
    const float* feat2   = (const float*)d_in[3];
    const float* t11_w   = (const float*)d_in[4];
    const float* t11_b   = (const float*)d_in[5];
    const float* t22_w   = (const float*)d_in[6];
    const float* t22_b   = (const float*)d_in[7];
    const float* pos1_w  = (const float*)d_in[8];
    const float* pos1_b  = (const float*)d_in[9];
    const float* gn1_g   = (const float*)d_in[10];
    const float* gn1_b   = (const float*)d_in[11];
    const float* m1a_w   = (const float*)d_in[12];
    const float* m1a_b   = (const float*)d_in[13];
    const float* m1a_g   = (const float*)d_in[14];
    const float* m1a_beta= (const float*)d_in[15];
    const float* m1b_w   = (const float*)d_in[16];
    const float* m1b_b   = (const float*)d_in[17];
    const float* m1b_g   = (const float*)d_in[18];
    const float* m1b_beta= (const float*)d_in[19];
    const float* t1_w    = (const float*)d_in[20];
    const float* t1_b    = (const float*)d_in[21];
    const float* t2_w    = (const float*)d_in[22];
    const float* t2_b    = (const float*)d_in[23];
    const float* pos2_w  = (const float*)d_in[24];
    const float* pos2_b  = (const float*)d_in[25];
    const float* gn2_g   = (const float*)d_in[26];
    const float* gn2_b   = (const float*)d_in[27];
    const float* m2a_w   = (const float*)d_in[28];
    const float* m2a_b   = (const float*)d_in[29];
    const float* m2a_g   = (const float*)d_in[30];
    const float* m2a_beta= (const float*)d_in[31];
    float* out = (float*)d_out;

    float *f1T,*f2T,*g1T,*g2T,*fn1T,*fn2T,*bufA,*bufB,*poolb,*stats,*WT,*dir12,*dir21;
    int *idx12,*idx21;
    cudaGetSymbolAddress((void**)&f1T,  g_f1T);
    cudaGetSymbolAddress((void**)&f2T,  g_f2T);
    cudaGetSymbolAddress((void**)&g1T,  g_g1T);
    cudaGetSymbolAddress((void**)&g2T,  g_g2T);
    cudaGetSymbolAddress((void**)&fn1T, g_fn1T);
    cudaGetSymbolAddress((void**)&fn2T, g_fn2T);
    cudaGetSymbolAddress((void**)&idx12,g_idx12);
    cudaGetSymbolAddress((void**)&idx21,g_idx21);
    cudaGetSymbolAddress((void**)&dir12,g_dir12);
    cudaGetSymbolAddress((void**)&dir21,g_dir21);
    cudaGetSymbolAddress((void**)&bufA, g_bufA);
    cudaGetSymbolAddress((void**)&bufB, g_bufB);
    cudaGetSymbolAddress((void**)&poolb,g_pool);
    cudaGetSymbolAddress((void**)&stats,g_stats);
    cudaGetSymbolAddress((void**)&WT,   g_WT);

    const int STB = BB*GG*2;   // stats floats per stage

    k_conv1d_in<<<dim3(NN/32, BB, 4), 128>>>(feat1, feat2, t11_w, t11_b, t22_w, t22_b);
    k_knn<<<dim3(NN/128, BB, 2), 128>>>(pc1, pc2);
    k_transw<<<3, 256>>>(m1a_w, m1b_w, m2a_w, stats);

    // ---- cross 1: queries pc1, cands pc2, p1=f1, p2=f2 ----
    k_gather<<<dim3(NN/8, BB), 128>>>(idx12, dir12, f1T, f2T, pos1_w, pos1_b, bufA, stats+0*STB);
    k_gemm<<<PP/128, 256>>>(bufA, WT+0*CC*CC, m1a_b, stats+0*STB, gn1_g, gn1_b, bufB, stats+1*STB);
    k_gemm<<<PP/128, 256>>>(bufB, WT+1*CC*CC, m1b_b, stats+1*STB, m1a_g, m1a_beta, bufA, stats+2*STB);
    k_pool<<<dim3(NN/32, BB), 128>>>(bufA, stats+2*STB, m1b_g, m1b_beta, poolb, nullptr);
    k_conv1d2<<<dim3(NN/32, BB), 128>>>(poolb, t1_w, t1_b, out, fn1T);

    // ---- cross 2: queries pc2, cands pc1, p1=g1, p2=g2 ----
    k_gather<<<dim3(NN/8, BB), 128>>>(idx21, dir21, g1T, g2T, pos1_w, pos1_b, bufA, stats+3*STB);
    k_gemm<<<PP/128, 256>>>(bufA, WT+0*CC*CC, m1a_b, stats+3*STB, gn1_g, gn1_b, bufB, stats+4*STB);
    k_gemm<<<PP/128, 256>>>(bufB, WT+1*CC*CC, m1b_b, stats+4*STB, m1a_g, m1a_beta, bufA, stats+5*STB);
    k_pool<<<dim3(NN/32, BB), 128>>>(bufA, stats+5*STB, m1b_g, m1b_beta, poolb, nullptr);
    k_conv1d2<<<dim3(NN/32, BB), 128>>>(poolb, t2_w, t2_b, out + BB*CC*NN, fn2T);

    // ---- cross 3: queries pc1, cands pc2, p1=feat1_new, p2=feat2_new ----
    k_gather<<<dim3(NN/8, BB), 128>>>(idx12, dir12, fn1T, fn2T, pos2_w, pos2_b, bufA, stats+6*STB);
    k_gemm<<<PP/128, 256>>>(bufA, WT+2*CC*CC, m2a_b, stats+6*STB, gn2_g, gn2_b, bufB, stats+7*STB);
    k_pool<<<dim3(NN/32, BB), 128>>>(bufB, stats+7*STB, m2a_g, m2a_beta, nullptr, out + 2*BB*CC*NN);
}